// round 1
// baseline (speedup 1.0000x reference)
#include <cuda_runtime.h>
#include <cstdint>

// ---------------------------------------------------------------------------
// FeatureAlign: offset conv (1x1) -> deformable conv v1 -> GroupNorm -> ReLU
// B=8, C=O=256, H=W=64, K=3, PAD=1, DG=4, GN_GROUPS=32, EPS=1e-5
//
// Phase A: sample bilinear taps into S[k=ch*9+k2][n=b*4096+hw]  (302 MB scratch)
// Phase B: SGEMM  out[o][n] = W[o][k] * S[k][n],  W = w_deform viewed [256][2304]
// Phase C: GroupNorm stats + normalize/ReLU in place on d_out
// ---------------------------------------------------------------------------

#define Bn 8
#define Cn 256
#define On 256
#define Hn 64
#define Wn 64
#define HW 4096           // Hn*Wn
#define DG 4
#define CG 64             // Cn/DG
#define K2 9
#define KDIM 2304         // Cn*K2
#define NDIM 32768        // Bn*HW

__device__ float g_S[(size_t)KDIM * NDIM];   // 302 MB sampling scratch
__device__ float g_stats[256 * 2];           // per (b, gn_group): mu, rsigma

// ---------------------------------------------------------------------------
// Phase A: bilinear sampling (fused 1x1 offset conv)
// grid: (hw_tiles=32, k2=9, b*DG+g=32), block: 128 threads (one pixel each)
// ---------------------------------------------------------------------------
__global__ void sample_kernel(const float* __restrict__ x,
                              const float* __restrict__ x_off,
                              const float* __restrict__ w_offset)
{
    const int hw = blockIdx.x * 128 + threadIdx.x;
    const int k2 = blockIdx.y;
    const int bg = blockIdx.z;
    const int b = bg >> 2;
    const int g = bg & 3;
    const int h = hw >> 6;
    const int w = hw & 63;

    // fused offset conv: offset[b][g*18 + k2*2 + {0,1}][hw]
    const float* xo = x_off + (size_t)b * 4 * HW + hw;
    const float o0 = xo[0], o1 = xo[HW], o2 = xo[2 * HW], o3 = xo[3 * HW];
    const float* wo = w_offset + (g * 18 + k2 * 2) * 4;
    const float offy = wo[0] * o0 + wo[1] * o1 + wo[2] * o2 + wo[3] * o3;
    const float offx = wo[4] * o0 + wo[5] * o1 + wo[6] * o2 + wo[7] * o3;

    const float py = (float)h + (float)(k2 / 3 - 1) + offy;
    const float px = (float)w + (float)(k2 % 3 - 1) + offx;
    const float fy = floorf(py), fx = floorf(px);
    const int y0 = (int)fy, x0 = (int)fx;
    const float wy = py - fy, wx = px - fx;

    float w00 = (1.f - wy) * (1.f - wx);
    float w01 = (1.f - wy) * wx;
    float w10 = wy * (1.f - wx);
    float w11 = wy * wx;

    const bool vy0 = (y0 >= 0) & (y0 < Hn);
    const bool vy1 = (y0 + 1 >= 0) & (y0 + 1 < Hn);
    const bool vx0 = (x0 >= 0) & (x0 < Wn);
    const bool vx1 = (x0 + 1 >= 0) & (x0 + 1 < Wn);
    w00 = (vy0 & vx0) ? w00 : 0.f;
    w01 = (vy0 & vx1) ? w01 : 0.f;
    w10 = (vy1 & vx0) ? w10 : 0.f;
    w11 = (vy1 & vx1) ? w11 : 0.f;

    const int yc0 = min(max(y0, 0), Hn - 1);
    const int yc1 = min(max(y0 + 1, 0), Hn - 1);
    const int xc0 = min(max(x0, 0), Wn - 1);
    const int xc1 = min(max(x0 + 1, 0), Wn - 1);
    const int i00 = yc0 * Wn + xc0;
    const int i01 = yc0 * Wn + xc1;
    const int i10 = yc1 * Wn + xc0;
    const int i11 = yc1 * Wn + xc1;

    const float* xp = x + ((size_t)b * Cn + g * CG) * HW;
    float* sp = g_S + ((size_t)(g * CG) * K2 + k2) * NDIM + b * HW + hw;

#pragma unroll 4
    for (int c = 0; c < CG; c++) {
        const float* xc = xp + c * HW;
        float v = w00 * __ldg(xc + i00) + w01 * __ldg(xc + i01)
                + w10 * __ldg(xc + i10) + w11 * __ldg(xc + i11);
        sp[(size_t)c * K2 * NDIM] = v;
    }
}

// ---------------------------------------------------------------------------
// Phase B: SGEMM  C[o][n] = sum_k A[o][k] * S[k][n]
// A = w_deform reinterpreted [256][2304].  Output written as [b][o][hw].
// BM=BN=128, BK=8, TM=TN=8, 256 threads.
// grid: (N/128=256, M/128=2)
// ---------------------------------------------------------------------------
__global__ void gemm_kernel(const float* __restrict__ A,
                            float* __restrict__ out)
{
    __shared__ float As[8][128];
    __shared__ float Bs[8][128];

    const int tid = threadIdx.x;
    const int bn = blockIdx.x;
    const int bm = blockIdx.y;
    const int n0 = bn * 128;

    const int arow = tid >> 1;         // 0..127
    const int acol = (tid & 1) * 4;    // 0 or 4
    const int brow = tid >> 5;         // 0..7
    const int bcol = (tid & 31) * 4;   // 0..124

    const int tx = tid & 15;
    const int ty = tid >> 4;

    float acc[8][8];
#pragma unroll
    for (int i = 0; i < 8; i++)
#pragma unroll
        for (int j = 0; j < 8; j++) acc[i][j] = 0.f;

    const float* Arow = A + (size_t)(bm * 128 + arow) * KDIM + acol;
    const float* Brow = g_S + (size_t)brow * NDIM + n0 + bcol;

    for (int k0 = 0; k0 < KDIM; k0 += 8) {
        float4 av = *(const float4*)(Arow + k0);
        As[acol + 0][arow] = av.x;
        As[acol + 1][arow] = av.y;
        As[acol + 2][arow] = av.z;
        As[acol + 3][arow] = av.w;
        float4 bv = *(const float4*)(Brow + (size_t)k0 * NDIM);
        *(float4*)(&Bs[brow][bcol]) = bv;
        __syncthreads();

#pragma unroll
        for (int kk = 0; kk < 8; kk++) {
            float rm[8], rn[8];
            *(float4*)(rm)     = *(const float4*)(&As[kk][ty * 8]);
            *(float4*)(rm + 4) = *(const float4*)(&As[kk][ty * 8 + 4]);
            *(float4*)(rn)     = *(const float4*)(&Bs[kk][tx * 8]);
            *(float4*)(rn + 4) = *(const float4*)(&Bs[kk][tx * 8 + 4]);
#pragma unroll
            for (int i = 0; i < 8; i++)
#pragma unroll
                for (int j = 0; j < 8; j++)
                    acc[i][j] = fmaf(rm[i], rn[j], acc[i][j]);
        }
        __syncthreads();
    }

    // write out: n = n0 + tx*8 + j  ->  b = n>>12, hw = n&4095 (b constant per block)
    const int b = n0 >> 12;
    const int hw0 = (n0 & 4095) + tx * 8;
#pragma unroll
    for (int i = 0; i < 8; i++) {
        const int o = bm * 128 + ty * 8 + i;
        float* op = out + (((size_t)b * On + o) << 12) + hw0;
        *(float4*)(op)     = make_float4(acc[i][0], acc[i][1], acc[i][2], acc[i][3]);
        *(float4*)(op + 4) = make_float4(acc[i][4], acc[i][5], acc[i][6], acc[i][7]);
    }
}

// ---------------------------------------------------------------------------
// Phase C1: GroupNorm statistics. One block per (b, group); region contiguous.
// ---------------------------------------------------------------------------
__global__ void gn_stats_kernel(const float* __restrict__ y)
{
    const int bgp = blockIdx.x;  // b*32 + grp
    const float* p = y + (size_t)bgp * 32768;
    const int tid = threadIdx.x;

    float s = 0.f, sq = 0.f;
    for (int i = tid * 4; i < 32768; i += 256 * 4) {
        float4 v = *(const float4*)(p + i);
        s  += v.x + v.y + v.z + v.w;
        sq += v.x * v.x + v.y * v.y + v.z * v.z + v.w * v.w;
    }

    __shared__ float ss[256], ssq[256];
    ss[tid] = s; ssq[tid] = sq;
    __syncthreads();
    for (int st = 128; st > 0; st >>= 1) {
        if (tid < st) { ss[tid] += ss[tid + st]; ssq[tid] += ssq[tid + st]; }
        __syncthreads();
    }
    if (tid == 0) {
        const float inv = 1.f / 32768.f;
        const float mu = ss[0] * inv;
        const float var = ssq[0] * inv - mu * mu;
        g_stats[bgp * 2 + 0] = mu;
        g_stats[bgp * 2 + 1] = rsqrtf(var + 1e-5f);
    }
}

// ---------------------------------------------------------------------------
// Phase C2: normalize + affine + ReLU (in place on d_out)
// ---------------------------------------------------------------------------
__global__ void gn_apply_kernel(float* __restrict__ y,
                                const float* __restrict__ gamma,
                                const float* __restrict__ beta)
{
    const int i = blockIdx.x * blockDim.x + threadIdx.x;  // float4 index
    const int e = i * 4;                                  // element index
    if (e >= Bn * On * HW) return;
    const int bgp = e >> 15;          // (b*256+o)*4096 / 32768 = b*32 + grp
    const int o = (e >> 12) & 255;
    const float mu = g_stats[bgp * 2 + 0];
    const float rs = g_stats[bgp * 2 + 1];
    const float ga = gamma[o] * rs;
    const float be = beta[o] - mu * ga;
    float4 v = *(float4*)(y + e);
    v.x = fmaxf(fmaf(v.x, ga, be), 0.f);
    v.y = fmaxf(fmaf(v.y, ga, be), 0.f);
    v.z = fmaxf(fmaf(v.z, ga, be), 0.f);
    v.w = fmaxf(fmaf(v.w, ga, be), 0.f);
    *(float4*)(y + e) = v;
}

// ---------------------------------------------------------------------------
extern "C" void kernel_launch(void* const* d_in, const int* in_sizes, int n_in,
                              void* d_out, int out_size)
{
    const float* x        = (const float*)d_in[0];  // [8,256,64,64]
    const float* x_off    = (const float*)d_in[1];  // [8,4,64,64]
    const float* w_offset = (const float*)d_in[2];  // [72,4]
    const float* w_deform = (const float*)d_in[3];  // [256,256,3,3] = [256][2304]
    const float* gamma    = (const float*)d_in[4];  // [256]
    const float* beta     = (const float*)d_in[5];  // [256]
    float* out = (float*)d_out;                     // [8,256,64,64]

    (void)in_sizes; (void)n_in; (void)out_size;

    // Phase A: sampling
    dim3 sgrid(HW / 128, K2, Bn * DG);
    sample_kernel<<<sgrid, 128>>>(x, x_off, w_offset);

    // Phase B: GEMM
    dim3 ggrid(NDIM / 128, On / 128);
    gemm_kernel<<<ggrid, 256>>>(w_deform, out);

    // Phase C: GroupNorm + ReLU
    gn_stats_kernel<<<256, 256>>>(out);
    gn_apply_kernel<<<(Bn * On * HW / 4 + 255) / 256, 256>>>(out, gamma, beta);
}

// round 3
// speedup vs baseline: 3.4092x; 3.4092x over previous
#include <cuda_runtime.h>
#include <cstdint>

// ---------------------------------------------------------------------------
// FeatureAlign: offset conv (1x1) -> deformable conv v1 -> GroupNorm -> ReLU
// sm_100 (plain compute_100 target: NO tcgen05/TMA — use mma.sync tf32)
//
// Phase A : sample bilinear taps (tf32-rounded) into S[k][n]   (302 MB scratch)
// Phase A': prep w_deform -> tf32 fragment-ordered g_A
// Phase B : tf32 mma.sync GEMM  out[o][n] = A[o][k] * S[k][n]
//           BM=256, BN=128, BK=16, 8 warps, 3-stage cp.async pipeline
// Phase C : GroupNorm stats + normalize/ReLU in place on d_out
// ---------------------------------------------------------------------------

#define Bn 8
#define Cn 256
#define On 256
#define Hn 64
#define Wn 64
#define HW 4096
#define DG 4
#define CG 64
#define K2 9
#define KDIM 2304
#define NDIM 32768

#define BM 256
#define BN 128
#define BK 16
#define ITERS (KDIM / BK)        // 144
#define NK8 (KDIM / 8)           // 288 k8-steps

__device__ float g_S[(size_t)KDIM * NDIM];        // [k][n] tf32-rounded samples
__device__ float g_A[(size_t)NK8 * 16 * 32 * 4];  // fragment-ordered weights (2.36 MB)
__device__ float g_stats[256 * 2];

// ------------------------------ helpers ------------------------------------
__device__ __forceinline__ uint32_t smem_u32(const void* p) {
    uint32_t a;
    asm("{ .reg .u64 t; cvta.to.shared.u64 t, %1; cvt.u32.u64 %0, t; }" : "=r"(a) : "l"(p));
    return a;
}
__device__ __forceinline__ float to_tf32(float v) {
    uint32_t r;
    asm("cvt.rna.tf32.f32 %0, %1;" : "=r"(r) : "f"(v));
    return __uint_as_float(r);
}
#define CP16(dst_u32, src_ptr) \
    asm volatile("cp.async.cg.shared.global [%0], [%1], 16;" :: "r"(dst_u32), "l"(src_ptr) : "memory")
#define CP_COMMIT() asm volatile("cp.async.commit_group;" ::: "memory")
#define CP_WAIT2()  asm volatile("cp.async.wait_group 2;" ::: "memory")

__device__ __forceinline__ void mma_tf32(float* c, const uint32_t* a, const uint32_t* b) {
    asm volatile(
        "mma.sync.aligned.m16n8k8.row.col.f32.tf32.tf32.f32 "
        "{%0,%1,%2,%3}, {%4,%5,%6,%7}, {%8,%9}, {%0,%1,%2,%3};"
        : "+f"(c[0]), "+f"(c[1]), "+f"(c[2]), "+f"(c[3])
        : "r"(a[0]), "r"(a[1]), "r"(a[2]), "r"(a[3]), "r"(b[0]), "r"(b[1]));
}

// ---------------------------------------------------------------------------
// Phase A: bilinear sampling (fused 1x1 offset conv), tf32-rounded output
// grid: (32, 9, 32)  block: 128
// ---------------------------------------------------------------------------
__global__ void sample_kernel(const float* __restrict__ x,
                              const float* __restrict__ x_off,
                              const float* __restrict__ w_offset)
{
    const int hw = blockIdx.x * 128 + threadIdx.x;
    const int k2 = blockIdx.y;
    const int bg = blockIdx.z;
    const int b = bg >> 2;
    const int g = bg & 3;
    const int h = hw >> 6;
    const int w = hw & 63;

    const float* xo = x_off + (size_t)b * 4 * HW + hw;
    const float o0 = xo[0], o1 = xo[HW], o2 = xo[2 * HW], o3 = xo[3 * HW];
    const float* wo = w_offset + (g * 18 + k2 * 2) * 4;
    const float offy = wo[0] * o0 + wo[1] * o1 + wo[2] * o2 + wo[3] * o3;
    const float offx = wo[4] * o0 + wo[5] * o1 + wo[6] * o2 + wo[7] * o3;

    const float py = (float)h + (float)(k2 / 3 - 1) + offy;
    const float px = (float)w + (float)(k2 % 3 - 1) + offx;
    const float fy = floorf(py), fx = floorf(px);
    const int y0 = (int)fy, x0 = (int)fx;
    const float wy = py - fy, wx = px - fx;

    float w00 = (1.f - wy) * (1.f - wx);
    float w01 = (1.f - wy) * wx;
    float w10 = wy * (1.f - wx);
    float w11 = wy * wx;

    const bool vy0 = (y0 >= 0) & (y0 < Hn);
    const bool vy1 = (y0 + 1 >= 0) & (y0 + 1 < Hn);
    const bool vx0 = (x0 >= 0) & (x0 < Wn);
    const bool vx1 = (x0 + 1 >= 0) & (x0 + 1 < Wn);
    w00 = (vy0 & vx0) ? w00 : 0.f;
    w01 = (vy0 & vx1) ? w01 : 0.f;
    w10 = (vy1 & vx0) ? w10 : 0.f;
    w11 = (vy1 & vx1) ? w11 : 0.f;

    const int yc0 = min(max(y0, 0), Hn - 1);
    const int yc1 = min(max(y0 + 1, 0), Hn - 1);
    const int xc0 = min(max(x0, 0), Wn - 1);
    const int xc1 = min(max(x0 + 1, 0), Wn - 1);
    const int i00 = yc0 * Wn + xc0;
    const int i01 = yc0 * Wn + xc1;
    const int i10 = yc1 * Wn + xc0;
    const int i11 = yc1 * Wn + xc1;

    const float* xp = x + ((size_t)b * Cn + g * CG) * HW;
    float* sp = g_S + ((size_t)(g * CG) * K2 + k2) * NDIM + b * HW + hw;

#pragma unroll 4
    for (int c = 0; c < CG; c++) {
        const float* xc = xp + c * HW;
        float v = w00 * __ldg(xc + i00) + w01 * __ldg(xc + i01)
                + w10 * __ldg(xc + i10) + w11 * __ldg(xc + i11);
        sp[(size_t)c * K2 * NDIM] = to_tf32(v);
    }
}

// ---------------------------------------------------------------------------
// Phase A': weight prep -> tf32, mma fragment order
// g_A[s][mt][lane] = float4{ A[m][k], A[m+8][k], A[m][k+4], A[m+8][k+4] }
//   m = mt*16 + lane/4, k = s*8 + lane%4
// ---------------------------------------------------------------------------
__global__ void prep_a_kernel(const float* __restrict__ wd)   // [256][2304]
{
    const int idx = blockIdx.x * 256 + threadIdx.x;           // < 288*16*32
    const int lane = idx & 31;
    const int mt = (idx >> 5) & 15;
    const int s = idx >> 9;
    const int m0 = mt * 16 + (lane >> 2);
    const int k0 = s * 8 + (lane & 3);
    float4 v;
    v.x = to_tf32(wd[(size_t)m0 * KDIM + k0]);
    v.y = to_tf32(wd[(size_t)(m0 + 8) * KDIM + k0]);
    v.z = to_tf32(wd[(size_t)m0 * KDIM + k0 + 4]);
    v.w = to_tf32(wd[(size_t)(m0 + 8) * KDIM + k0 + 4]);
    ((float4*)g_A)[idx] = v;
}

// ---------------------------------------------------------------------------
// Phase B: tf32 mma.sync GEMM.  grid = 256 (N tiles), block = 256 (8 warps)
// warp tile 64x64: warp_m = wid&3, warp_n = wid>>2
// smem: A fragment-ordered [stage][2 k8][16 mt][32 lane][4]  (16 KB/stage)
//       B [stage][16 k][136 n-padded]                        (8.7 KB/stage)
// ---------------------------------------------------------------------------
#define A_ST_F 4096        // floats per A stage
#define B_ST_F 2176        // floats per B stage (16*136)
#define GEMM_SMEM ((3 * (A_ST_F + B_ST_F)) * 4)

__global__ void __launch_bounds__(256, 1) gemm_kernel(float* __restrict__ out)
{
    extern __shared__ float smemf[];
    float* sBf = smemf + 3 * A_ST_F;
    const uint32_t sA_u = smem_u32(smemf);
    const uint32_t sB_u = smem_u32(sBf);

    const int tid = threadIdx.x;
    const int wid = tid >> 5;
    const int lane = tid & 31;
    const int g = lane >> 2;
    const int l4 = lane & 3;
    const int wm = wid & 3;
    const int wn = wid >> 2;
    const int n0 = blockIdx.x * BN;

    float acc[4][8][4];
#pragma unroll
    for (int i = 0; i < 4; i++)
#pragma unroll
        for (int j = 0; j < 8; j++)
#pragma unroll
            for (int q = 0; q < 4; q++) acc[i][j][q] = 0.f;

    // ---- producer ----
    auto load_stage = [&](int iter, int s) {
        const float4* srcA = (const float4*)g_A + (size_t)iter * 1024;
        const uint32_t dA = sA_u + (uint32_t)s * (A_ST_F * 4);
#pragma unroll
        for (int j = 0; j < 4; j++) {
            const int idx = j * 256 + tid;
            CP16(dA + idx * 16, srcA + idx);
        }
        const float* srcB = g_S + (size_t)(iter * BK) * NDIM + n0;
        const uint32_t dB = sB_u + (uint32_t)s * (B_ST_F * 4);
#pragma unroll
        for (int j = 0; j < 2; j++) {
            const int idx = j * 256 + tid;
            const int r = idx >> 5;
            const int c4 = idx & 31;
            CP16(dB + (r * 136 + c4 * 4) * 4, srcB + (size_t)r * NDIM + c4 * 4);
        }
        CP_COMMIT();
    };

    load_stage(0, 0);
    load_stage(1, 1);
    load_stage(2, 2);

    for (int iter = 0; iter < ITERS; iter++) {
        const int s = iter % 3;
        CP_WAIT2();
        __syncthreads();

        const uint32_t aS = sA_u + (uint32_t)s * (A_ST_F * 4);
        const float* bS = sBf + s * B_ST_F;

#pragma unroll
        for (int k8 = 0; k8 < 2; k8++) {
            uint32_t af[4][4];
#pragma unroll
            for (int i = 0; i < 4; i++) {
                const uint32_t addr = aS + (((k8 * 16 + wm * 4 + i) * 32 + lane) << 4);
                asm volatile("ld.shared.v4.b32 {%0,%1,%2,%3}, [%4];"
                             : "=r"(af[i][0]), "=r"(af[i][1]), "=r"(af[i][2]), "=r"(af[i][3])
                             : "r"(addr));
            }
            uint32_t bf[8][2];
            const int r0 = k8 * 8 + l4;
            const float* bp = bS + wn * 64 + g;
#pragma unroll
            for (int j = 0; j < 8; j++) {
                bf[j][0] = __float_as_uint(bp[r0 * 136 + j * 8]);
                bf[j][1] = __float_as_uint(bp[(r0 + 4) * 136 + j * 8]);
            }
#pragma unroll
            for (int i = 0; i < 4; i++)
#pragma unroll
                for (int j = 0; j < 8; j++)
                    mma_tf32(acc[i][j], af[i], bf[j]);
        }
        __syncthreads();
        if (iter + 3 < ITERS) load_stage(iter + 3, s);
        else CP_COMMIT();   // keep wait_group accounting consistent
    }

    // ---- epilogue: C -> out[b][o][hw] ----
    const int b = n0 >> 12;
    const int hw0 = (n0 & 4095) + wn * 64 + l4 * 2;
#pragma unroll
    for (int i = 0; i < 4; i++) {
        const int o0 = wm * 64 + i * 16 + g;
        float* p0 = out + (((size_t)b * On + o0) << 12) + hw0;
        float* p1 = out + (((size_t)b * On + o0 + 8) << 12) + hw0;
#pragma unroll
        for (int j = 0; j < 8; j++) {
            *(float2*)(p0 + j * 8) = make_float2(acc[i][j][0], acc[i][j][1]);
            *(float2*)(p1 + j * 8) = make_float2(acc[i][j][2], acc[i][j][3]);
        }
    }
}

// ---------------------------------------------------------------------------
// Phase C1: GroupNorm statistics (one block per (b, group), contiguous 32768)
// ---------------------------------------------------------------------------
__global__ void gn_stats_kernel(const float* __restrict__ y)
{
    const int bgp = blockIdx.x;
    const float* p = y + (size_t)bgp * 32768;
    const int tid = threadIdx.x;

    float s = 0.f, sq = 0.f;
    for (int i = tid * 4; i < 32768; i += 256 * 4) {
        float4 v = *(const float4*)(p + i);
        s  += v.x + v.y + v.z + v.w;
        sq += v.x * v.x + v.y * v.y + v.z * v.z + v.w * v.w;
    }

    __shared__ float ss[256], ssq[256];
    ss[tid] = s; ssq[tid] = sq;
    __syncthreads();
    for (int st = 128; st > 0; st >>= 1) {
        if (tid < st) { ss[tid] += ss[tid + st]; ssq[tid] += ssq[tid + st]; }
        __syncthreads();
    }
    if (tid == 0) {
        const float inv = 1.f / 32768.f;
        const float mu = ss[0] * inv;
        const float var = ssq[0] * inv - mu * mu;
        g_stats[bgp * 2 + 0] = mu;
        g_stats[bgp * 2 + 1] = rsqrtf(var + 1e-5f);
    }
}

// ---------------------------------------------------------------------------
// Phase C2: normalize + affine + ReLU (in place)
// ---------------------------------------------------------------------------
__global__ void gn_apply_kernel(float* __restrict__ y,
                                const float* __restrict__ gamma,
                                const float* __restrict__ beta)
{
    const int i = blockIdx.x * blockDim.x + threadIdx.x;
    const int e = i * 4;
    if (e >= Bn * On * HW) return;
    const int bgp = e >> 15;
    const int o = (e >> 12) & 255;
    const float mu = g_stats[bgp * 2 + 0];
    const float rs = g_stats[bgp * 2 + 1];
    const float ga = gamma[o] * rs;
    const float be = beta[o] - mu * ga;
    float4 v = *(float4*)(y + e);
    v.x = fmaxf(fmaf(v.x, ga, be), 0.f);
    v.y = fmaxf(fmaf(v.y, ga, be), 0.f);
    v.z = fmaxf(fmaf(v.z, ga, be), 0.f);
    v.w = fmaxf(fmaf(v.w, ga, be), 0.f);
    *(float4*)(y + e) = v;
}

// ---------------------------------------------------------------------------
extern "C" void kernel_launch(void* const* d_in, const int* in_sizes, int n_in,
                              void* d_out, int out_size)
{
    const float* x        = (const float*)d_in[0];
    const float* x_off    = (const float*)d_in[1];
    const float* w_offset = (const float*)d_in[2];
    const float* w_deform = (const float*)d_in[3];
    const float* gamma    = (const float*)d_in[4];
    const float* beta     = (const float*)d_in[5];
    float* out = (float*)d_out;

    (void)in_sizes; (void)n_in; (void)out_size;

    cudaFuncSetAttribute(gemm_kernel, cudaFuncAttributeMaxDynamicSharedMemorySize, GEMM_SMEM);

    prep_a_kernel<<<NK8 * 16 * 32 / 256, 256>>>(w_deform);

    dim3 sgrid(HW / 128, K2, Bn * DG);
    sample_kernel<<<sgrid, 128>>>(x, x_off, w_offset);

    gemm_kernel<<<NDIM / BN, 256, GEMM_SMEM>>>(out);

    gn_stats_kernel<<<256, 256>>>(out);
    gn_apply_kernel<<<(Bn * On * HW / 4 + 255) / 256, 256>>>(out, gamma, beta);
}